// round 14
// baseline (speedup 1.0000x reference)
#include <cuda_runtime.h>
#include <math.h>

#define B0V      8
#define CINV     256
#define LSEQ     9216
#define DMV      32
#define DINV     64
#define DSTATEV  64
#define NHV      8
#define HDV      8
#define CONVCH   192
#define DPROJ    264
#define CHUNKV   32
#define NCHUNKV  288
#define NSEQV    64
#define DOUTV    256

// ---------------- scratch ----------------
__device__ float g_xs[(size_t)NSEQV*LSEQ*DMV];
__device__ float g_y0[(size_t)NSEQV*LSEQ*DINV];
__device__ float g_Cm[(size_t)NSEQV*LSEQ*DSTATEV];
__device__ float g_zs[(size_t)NSEQV*LSEQ*DINV];
__device__ float g_ea[(size_t)NSEQV*LSEQ*NHV];
__device__ float g_st[(size_t)NSEQV*NCHUNKV*NHV*HDV*DSTATEV];
__device__ float g_cd[(size_t)NSEQV*NCHUNKV*NHV];
__device__ float g_ym[(size_t)B0V*LSEQ*CINV];

__device__ __forceinline__ float siluf(float v) { return v / (1.f + __expf(-v)); }

// ============ k1: LN over C + split-transpose ============
// launched as 3 slices of grid (96, 8) with xoff = 0/96/192 (profiler phase shift)
__global__ __launch_bounds__(256) void k1_ln_split(
    const float* __restrict__ x, const float* __restrict__ lw,
    const float* __restrict__ lb, int xoff) {
  __shared__ float tile[256*33];
  __shared__ float s_mu[32], s_rs[32];
  int b = blockIdx.y;
  int l0 = (blockIdx.x + xoff) * 32;
  int tid = threadIdx.x;

  for (int i = tid; i < 256*32; i += 256) {
    int c = i >> 5, l = i & 31;
    tile[c*33 + l] = x[((size_t)(b*CINV + c))*LSEQ + l0 + l];
  }
  __syncthreads();
  {
    int w = tid >> 5, lane = tid & 31;
    for (int q = 0; q < 4; q++) {
      int l = w*4 + q;
      float s = 0.f, ss = 0.f;
      #pragma unroll
      for (int j = 0; j < 8; j++) {
        float v = tile[(lane + 32*j)*33 + l];
        s += v; ss += v*v;
      }
      #pragma unroll
      for (int o = 16; o > 0; o >>= 1) {
        s  += __shfl_xor_sync(0xffffffffu, s,  o);
        ss += __shfl_xor_sync(0xffffffffu, ss, o);
      }
      if (lane == 0) {
        float mu = s * (1.f/256.f);
        float var = ss * (1.f/256.f) - mu*mu;
        s_mu[l] = mu;
        s_rs[l] = rsqrtf(var + 1e-5f);
      }
    }
  }
  __syncthreads();
  for (int i = tid; i < 256*32; i += 256) {
    int cg = i >> 10;
    int l  = (i >> 5) & 31;
    int j  = i & 31;
    int c  = cg*32 + j;
    float v = (tile[c*33 + l] - s_mu[l]) * s_rs[l] * lw[c] + lb[c];
    int seq = cg*B0V + b;
    g_xs[((size_t)seq*LSEQ + l0 + l)*DMV + j] = v;
  }
}

// ============ k2: in_proj + conv + intra-chunk SSD ============
// smem 12944 floats = 51.8KB -> 4 blocks/SM.
// phase-A: sXT[32][36]@0, sWs[32][88]@1152, sZX[34][264]@3968
// phase-B: sDT@0, sAC@256, sED@520, sE1@776,
//          sXH@1152, sB@3200, sC[32][68]@5248, sXDT@7424, sG@9472, sCF[32][68]@10528
#define SM2_FLOATS 12944
#define SM2_BYTES (SM2_FLOATS * 4)
#define ZXB 3968

__global__ __launch_bounds__(256, 4) void k2_chunk(
    const float* __restrict__ W_in, const float* __restrict__ conv_w,
    const float* __restrict__ conv_b, const float* __restrict__ dt_bias,
    const float* __restrict__ A_log, const float* __restrict__ Dp) {
  extern __shared__ float sm[];
  float* sXT  = sm;             // [32][36]
  float* sWs  = sm + 1152;      // [32][88]
  float* sZX  = sm + ZXB;       // [34][264]
  // phase-B aliases
  float* sDT  = sm;             // [32][8]
  float* sAC  = sm + 256;       // [8][33]
  float* sED  = sm + 520;      // [8][32]
  float* sE1  = sm + 776;      // [8][32]
  float* sXH  = sm + 1152;     // [32][64]
  float* sB   = sm + 3200;     // [32][64]
  float* sC   = sm + 5248;     // [32][68]
  float* sXDT = sm + 7424;     // [32][64]
  float* sG   = sm + 9472;     // [32][33]
  float* sCF  = sm + 10528;    // [32][68]

  int chunk = blockIdx.x;
  int seq   = blockIdx.y;
  int c0 = chunk * CHUNKV;
  int tid = threadIdx.x;

  // prefetch W slab 0 into regs
  float wreg[11];
  #pragma unroll
  for (int j = 0; j < 11; j++) {
    int i = tid + j*256;
    int k = i / 88, col = i - k*88;
    wreg[j] = W_in[k*DPROJ + col];
  }

  // load x^T tile
  for (int i = tid; i < 36*32; i += 256) {
    int r = i >> 5, k = i & 31;
    int l = c0 - 2 + r;
    float v = 0.f;
    if (r < 34 && l >= 0) v = g_xs[((size_t)seq*LSEQ + l)*DMV + k];
    sXT[k*36 + r] = v;
  }
  __syncthreads();

  // in_proj GEMM in 3 slabs, 4r x 8n tiles, 99 active threads,
  // reg double-buffered W
  for (int s = 0; s < 3; s++) {
    int gbase = s*88;
    #pragma unroll
    for (int j = 0; j < 11; j++) sWs[tid + j*256] = wreg[j];
    __syncthreads();
    if (s < 2) {
      int gnext = gbase + 88;
      #pragma unroll
      for (int j = 0; j < 11; j++) {
        int i = tid + j*256;
        int k = i / 88, col = i - k*88;
        wreg[j] = W_in[k*DPROJ + gnext + col];
      }
    }
    if (tid < 99) {
      int rt = tid / 11, ct = tid - rt*11;   // rt 0..8, ct 0..10
      int r0 = rt*4, n0 = ct*8;
      float acc[4][8];
      #pragma unroll
      for (int i = 0; i < 4; i++)
        #pragma unroll
        for (int j = 0; j < 8; j++) acc[i][j] = 0.f;
      #pragma unroll 4
      for (int k = 0; k < 32; k++) {
        float4 xv = *(const float4*)&sXT[k*36 + r0];
        float4 w0 = *(const float4*)&sWs[k*88 + n0];
        float4 w1 = *(const float4*)&sWs[k*88 + n0 + 4];
        float xr[4] = {xv.x, xv.y, xv.z, xv.w};
        float wr[8] = {w0.x,w0.y,w0.z,w0.w, w1.x,w1.y,w1.z,w1.w};
        #pragma unroll
        for (int i = 0; i < 4; i++)
          #pragma unroll
          for (int j = 0; j < 8; j++) acc[i][j] += xr[i]*wr[j];
      }
      #pragma unroll
      for (int i = 0; i < 4; i++) {
        int r = r0 + i;
        if (r < 34) {
          *(float4*)&sZX[r*DPROJ + gbase + n0] =
            make_float4(acc[i][0],acc[i][1],acc[i][2],acc[i][3]);
          *(float4*)&sZX[r*DPROJ + gbase + n0 + 4] =
            make_float4(acc[i][4],acc[i][5],acc[i][6],acc[i][7]);
        }
      }
    }
    __syncthreads();
  }

  // conv(3)+silu into registers; z and dt in the same phase
  float creg[24];
  #pragma unroll
  for (int j = 0; j < 24; j++) {
    int i = j*256 + tid;
    int l = i / CONVCH, c = i - l*CONVCH;
    float v = conv_w[c*3+0]*sZX[ l   *DPROJ + 64 + c]
            + conv_w[c*3+1]*sZX[(l+1)*DPROJ + 64 + c]
            + conv_w[c*3+2]*sZX[(l+2)*DPROJ + 64 + c]
            + conv_b[c];
    v = siluf(v);
    creg[j] = v;
    if (c >= 128)
      g_Cm[((size_t)seq*LSEQ + c0 + l)*DSTATEV + (c-128)] = v;
  }
  for (int i = tid; i < 32*64; i += 256) {
    int l = i >> 6, j = i & 63;
    g_zs[((size_t)seq*LSEQ + c0 + l)*DINV + j] = siluf(sZX[(l+2)*DPROJ + j]);
  }
  {
    int l = tid >> 3, h = tid & 7;
    float raw = sZX[(l+2)*DPROJ + 256 + h] + dt_bias[h];
    sDT[l*8 + h] = (raw > 20.f) ? raw : log1pf(__expf(raw));
  }
  __syncthreads();

  // scatter conv outputs (ZX/W regions now dead)
  #pragma unroll
  for (int j = 0; j < 24; j++) {
    int i = j*256 + tid;
    int l = i / CONVCH, c = i - l*CONVCH;
    if (c < 64)       sXH[l*64 + c] = creg[j];
    else if (c < 128) sB[l*64 + (c-64)] = creg[j];
    else              sC[l*68 + (c-128)] = creg[j];
  }
  // per-head inclusive scan via warp shuffles
  {
    int w = tid >> 5, lane = tid & 31;
    float Ah = -__expf(A_log[w]);
    float dt = sDT[lane*8 + w];
    float a  = dt * Ah;
    float e1 = __expf(a);
    #pragma unroll
    for (int o = 1; o < 32; o <<= 1) {
      float v = __shfl_up_sync(0xffffffffu, a, o);
      if (lane >= o) a += v;
    }
    sAC[w*33 + lane] = a;
    float alast = __shfl_sync(0xffffffffu, a, 31);
    sED[w*32 + lane] = __expf(alast - a);
    sE1[w*32 + lane] = e1;
    if (lane == 31) g_cd[((size_t)seq*NCHUNKV + chunk)*NHV + w] = __expf(a);
  }
  __syncthreads();

  // XDT + CF (states coefficients) + g_ea
  for (int i = tid; i < 32*64; i += 256) {
    int l = i >> 6, d = i & 63;
    float v = sXH[l*64+d]*sDT[l*8 + (d>>3)];
    sXDT[l*64+d] = v;
    sCF[l*68+d]  = v * sED[(d>>3)*32 + l];
  }
  {
    int l = tid >> 3, h = tid & 7;
    g_ea[((size_t)seq*LSEQ + c0 + l)*NHV + h] = __expf(sAC[h*33+l]);
  }
  __syncthreads();

  // G[l][s] = C_l . B_s, vectorized float4 over n
  {
    int w = tid >> 5, l = tid & 31;
    float a0=0.f,a1=0.f,a2=0.f,a3=0.f;
    int s0=w, s1=w+8, s2=w+16, s3=w+24;
    #pragma unroll 4
    for (int n4 = 0; n4 < 64; n4 += 4) {
      float4 cv = *(const float4*)&sC[l*68+n4];
      float4 b0 = *(const float4*)&sB[s0*64+n4];
      float4 b1 = *(const float4*)&sB[s1*64+n4];
      float4 b2 = *(const float4*)&sB[s2*64+n4];
      float4 b3 = *(const float4*)&sB[s3*64+n4];
      a0 += cv.x*b0.x + cv.y*b0.y + cv.z*b0.z + cv.w*b0.w;
      a1 += cv.x*b1.x + cv.y*b1.y + cv.z*b1.z + cv.w*b1.w;
      a2 += cv.x*b2.x + cv.y*b2.y + cv.z*b2.z + cv.w*b2.w;
      a3 += cv.x*b3.x + cv.y*b3.y + cv.z*b3.z + cv.w*b3.w;
    }
    sG[l*33+s0]=a0; sG[l*33+s1]=a1; sG[l*33+s2]=a2; sG[l*33+s3]=a3;
  }
  __syncthreads();

  // chunk states as 4hp x 4n GEMM over sCF/sB
  {
    int nt = tid & 15, ht = tid >> 4;
    int n0 = nt*4, hp0 = ht*4;
    float acc[4][4];
    #pragma unroll
    for (int i = 0; i < 4; i++)
      #pragma unroll
      for (int j = 0; j < 4; j++) acc[i][j] = 0.f;
    #pragma unroll 4
    for (int l = 0; l < 32; l++) {
      float4 cf = *(const float4*)&sCF[l*68 + hp0];
      float4 bv = *(const float4*)&sB[l*64 + n0];
      float cr[4] = {cf.x, cf.y, cf.z, cf.w};
      float br[4] = {bv.x, bv.y, bv.z, bv.w};
      #pragma unroll
      for (int i = 0; i < 4; i++)
        #pragma unroll
        for (int j = 0; j < 4; j++) acc[i][j] += cr[i]*br[j];
    }
    size_t sbase = (((size_t)seq*NCHUNKV + chunk)*NHV)*(HDV*DSTATEV);
    #pragma unroll
    for (int i = 0; i < 4; i++)
      *(float4*)&g_st[sbase + (size_t)(hp0+i)*64 + n0] =
        make_float4(acc[i][0],acc[i][1],acc[i][2],acc[i][3]);
  }

  // Yd + D term: decay as running product
  {
    int l = tid >> 3, h = tid & 7;
    float acc[8];
    #pragma unroll
    for (int p = 0; p < 8; p++) acc[p] = Dp[h]*sXH[l*64 + h*8 + p];
    const float* e1 = sE1 + h*32;
    float w = 1.f;
    for (int s = l; s >= 0; s--) {
      float wgt = sG[l*33+s] * w;
      float4 xa = *(const float4*)&sXDT[s*64 + h*8];
      float4 xb = *(const float4*)&sXDT[s*64 + h*8 + 4];
      acc[0]+=wgt*xa.x; acc[1]+=wgt*xa.y; acc[2]+=wgt*xa.z; acc[3]+=wgt*xa.w;
      acc[4]+=wgt*xb.x; acc[5]+=wgt*xb.y; acc[6]+=wgt*xb.z; acc[7]+=wgt*xb.w;
      w *= e1[s];
    }
    size_t ob = ((size_t)seq*LSEQ + c0 + l)*DINV + h*8;
    *(float4*)&g_y0[ob]   = make_float4(acc[0],acc[1],acc[2],acc[3]);
    *(float4*)&g_y0[ob+4] = make_float4(acc[4],acc[5],acc[6],acc[7]);
  }
}

// ============ k3: inter-chunk scan (states -> prev, in place) ============
__global__ __launch_bounds__(128) void k3_scan() {
  int bid = blockIdx.x;
  int seq = bid >> 3, h = bid & 7;
  int e = threadIdx.x * 4;
  size_t base = (((size_t)seq*NCHUNKV)*NHV + h)*(HDV*DSTATEV) + e;
  size_t cdb  = (size_t)seq*NCHUNKV*NHV + h;
  const size_t CS = (size_t)NHV*HDV*DSTATEV;
  float4 carry = make_float4(0.f,0.f,0.f,0.f);
  for (int c = 0; c < NCHUNKV; c += 4) {
    float4 s0 = *(float4*)&g_st[base];
    float4 s1 = *(float4*)&g_st[base + CS];
    float4 s2 = *(float4*)&g_st[base + 2*CS];
    float4 s3 = *(float4*)&g_st[base + 3*CS];
    float d0 = g_cd[cdb], d1 = g_cd[cdb+8], d2 = g_cd[cdb+16], d3 = g_cd[cdb+24];
    *(float4*)&g_st[base] = carry;
    carry.x = carry.x*d0 + s0.x; carry.y = carry.y*d0 + s0.y;
    carry.z = carry.z*d0 + s0.z; carry.w = carry.w*d0 + s0.w;
    *(float4*)&g_st[base + CS] = carry;
    carry.x = carry.x*d1 + s1.x; carry.y = carry.y*d1 + s1.y;
    carry.z = carry.z*d1 + s1.z; carry.w = carry.w*d1 + s1.w;
    *(float4*)&g_st[base + 2*CS] = carry;
    carry.x = carry.x*d2 + s2.x; carry.y = carry.y*d2 + s2.y;
    carry.z = carry.z*d2 + s2.z; carry.w = carry.w*d2 + s2.w;
    *(float4*)&g_st[base + 3*CS] = carry;
    carry.x = carry.x*d3 + s3.x; carry.y = carry.y*d3 + s3.y;
    carry.z = carry.z*d3 + s3.z; carry.w = carry.w*d3 + s3.w;
    base += 4*CS; cdb += 32;
  }
}

// ============ k4: two chunks/block, phase-aliased smem (52KB, 4 blocks/SM) ====
#define SM4_FLOATS 12992
#define SM4_BYTES (SM4_FLOATS * 4)
__global__ __launch_bounds__(256, 4) void k4_tail(
    const float* __restrict__ rms_w, const float* __restrict__ W_out,
    const float* __restrict__ skip_scale) {
  extern __shared__ float s4[];
  float* sPrev = s4;            // ch*4352 + n*68 + hp
  float* sC    = s4 + 8704;     // l*66 + n
  float* sY    = s4;            // l*68 + hp   (phase 2)
  float* sWo   = s4 + 8704;     // d*32 + m    (phase 2)
  float* sRS   = s4 + 12928;    // [64]
  int cp = blockIdx.x, seq = blockIdx.y;
  int c0 = cp * 64;
  int tid = threadIdx.x;
  float skip = skip_scale[0];

  {
    size_t stb = (((size_t)seq*NCHUNKV + cp*2)*NHV)*(HDV*DSTATEV);
    for (int i = tid; i < 8192; i += 256) {
      int ch = i >> 12, r = i & 4095;
      int hp = r >> 6, n = r & 63;
      sPrev[ch*4352 + n*68 + hp] = g_st[stb + (size_t)ch*4096 + (size_t)hp*64 + n];
    }
  }
  for (int i = tid; i < 4096; i += 256) {
    int l = i >> 6, n = i & 63;
    sC[l*66+n] = g_Cm[((size_t)seq*LSEQ + c0 + l)*DSTATEV + n];
  }
  __syncthreads();

  float yv[4][4];
  int ht = tid & 15, lt = tid >> 4;
  int l0g = lt*4, hp0 = ht*4;
  {
    int ch = lt >> 3;
    const float* Cb = sC + l0g*66;
    const float* Pb = sPrev + ch*4352 + hp0;
    float acc[4][4];
    #pragma unroll
    for (int i = 0; i < 4; i++)
      #pragma unroll
      for (int j = 0; j < 4; j++) acc[i][j] = 0.f;
    #pragma unroll 4
    for (int n = 0; n < 64; n++) {
      float4 pv = *(const float4*)&Pb[n*68];
      float c0v = Cb[n], c1v = Cb[66+n], c2v = Cb[132+n], c3v = Cb[198+n];
      acc[0][0]+=c0v*pv.x; acc[0][1]+=c0v*pv.y; acc[0][2]+=c0v*pv.z; acc[0][3]+=c0v*pv.w;
      acc[1][0]+=c1v*pv.x; acc[1][1]+=c1v*pv.y; acc[1][2]+=c1v*pv.z; acc[1][3]+=c1v*pv.w;
      acc[2][0]+=c2v*pv.x; acc[2][1]+=c2v*pv.y; acc[2][2]+=c2v*pv.z; acc[2][3]+=c2v*pv.w;
      acc[3][0]+=c3v*pv.x; acc[3][1]+=c3v*pv.y; acc[3][2]+=c3v*pv.z; acc[3][3]+=c3v*pv.w;
    }
    int h = hp0 >> 3;
    #pragma unroll
    for (int i = 0; i < 4; i++) {
      int l = l0g + i;
      size_t row = (size_t)seq*LSEQ + c0 + l;
      float ea = g_ea[row*NHV + h];
      float4 y0 = *(const float4*)&g_y0[row*DINV + hp0];
      float4 zz = *(const float4*)&g_zs[row*DINV + hp0];
      yv[i][0] = (y0.x + ea*acc[i][0])*zz.x;
      yv[i][1] = (y0.y + ea*acc[i][1])*zz.y;
      yv[i][2] = (y0.z + ea*acc[i][2])*zz.z;
      yv[i][3] = (y0.w + ea*acc[i][3])*zz.w;
    }
  }
  __syncthreads();
  #pragma unroll
  for (int i = 0; i < 4; i++)
    *(float4*)&sY[(l0g+i)*68 + hp0] = make_float4(yv[i][0],yv[i][1],yv[i][2],yv[i][3]);
  for (int i = tid; i < 2048; i += 256) sWo[i] = W_out[i];
  __syncthreads();

  {
    int w = tid >> 5, lane = tid & 31;
    for (int q = 0; q < 8; q++) {
      int l = w*8 + q;
      float v1 = sY[l*68 + lane], v2 = sY[l*68 + lane + 32];
      float ss = v1*v1 + v2*v2;
      #pragma unroll
      for (int o = 16; o > 0; o >>= 1) ss += __shfl_xor_sync(0xffffffffu, ss, o);
      if (lane == 0) sRS[l] = rsqrtf(ss*(1.f/64.f) + 1e-5f);
    }
  }
  __syncthreads();
  for (int i = tid; i < 4096; i += 256) {
    int l = i >> 6, d = i & 63;
    sY[l*68+d] *= sRS[l]*rms_w[d];
  }
  __syncthreads();
  {
    int mt = tid & 15, lt2 = tid >> 4;
    int l0 = lt2*4, m0 = mt*2;
    float acc[4][2];
    #pragma unroll
    for (int i = 0; i < 4; i++) { acc[i][0] = 0.f; acc[i][1] = 0.f; }
    const float* Yb = sY + l0*68;
    #pragma unroll 4
    for (int d = 0; d < 64; d++) {
      float2 wv = *(const float2*)&sWo[d*32 + m0];
      float y0v = Yb[d], y1v = Yb[68+d], y2v = Yb[136+d], y3v = Yb[204+d];
      acc[0][0]+=y0v*wv.x; acc[0][1]+=y0v*wv.y;
      acc[1][0]+=y1v*wv.x; acc[1][1]+=y1v*wv.y;
      acc[2][0]+=y2v*wv.x; acc[2][1]+=y2v*wv.y;
      acc[3][0]+=y3v*wv.x; acc[3][1]+=y3v*wv.y;
    }
    int split = seq >> 3, b = seq & 7;
    #pragma unroll
    for (int i = 0; i < 4; i++) {
      int l = l0 + i;
      float2 xk = *(const float2*)&g_xs[((size_t)seq*LSEQ + c0 + l)*DMV + m0];
      float2 ov;
      ov.x = acc[i][0] + skip*xk.x;
      ov.y = acc[i][1] + skip*xk.y;
      *(float2*)&g_ym[((size_t)b*LSEQ + c0 + l)*CINV + split*32 + m0] = ov;
    }
  }
}

// ============ k5: LN + 256x256 projection, reg-double-buffered W slabs ====
#define SM5_FLOATS 26880
#define SM5_BYTES (SM5_FLOATS * 4)
__global__ __launch_bounds__(256, 2) void k5_out(
    const float* __restrict__ lw, const float* __restrict__ lb,
    const float* __restrict__ proj_w, const float* __restrict__ proj_b,
    float* __restrict__ out) {
  extern __shared__ float sm[];
  float* sX = sm;           // [64][260]
  float* sW = sm + 16640;   // [32][320] swizzled: addr = k*320 + (o>>4)*20 + (o&15)
  int b = blockIdx.y;
  int l0 = blockIdx.x * 64;
  int tid = threadIdx.x;

  float wbuf[32];
  #pragma unroll
  for (int j = 0; j < 32; j++) {
    int i = tid + j*256;
    int k = i >> 8, o = i & 255;
    wbuf[j] = proj_w[(size_t)k*DOUTV + o];
  }

  for (int i = tid; i < 64*256; i += 256) {
    int l = i >> 8, c = i & 255;
    sX[l*260 + c] = g_ym[((size_t)b*LSEQ + l0 + l)*CINV + c];
  }
  __syncthreads();
  {
    int w = tid >> 5, lane = tid & 31;
    for (int q = 0; q < 8; q++) {
      int l = w*8 + q;
      float s = 0.f, ss = 0.f;
      #pragma unroll
      for (int j = 0; j < 8; j++) {
        float v = sX[l*260 + lane + 32*j];
        s += v; ss += v*v;
      }
      #pragma unroll
      for (int o = 16; o > 0; o >>= 1) {
        s  += __shfl_xor_sync(0xffffffffu, s,  o);
        ss += __shfl_xor_sync(0xffffffffu, ss, o);
      }
      float mu = s * (1.f/256.f);
      float rs = rsqrtf(ss*(1.f/256.f) - mu*mu + 1e-5f);
      #pragma unroll
      for (int j = 0; j < 8; j++) {
        int c = lane + 32*j;
        sX[l*260 + c] = (sX[l*260 + c] - mu)*rs*lw[c] + lb[c];
      }
    }
  }
  __syncthreads();

  int ot = tid & 15, lt = tid >> 4;
  float acc[4][16];
  #pragma unroll
  for (int i = 0; i < 4; i++)
    #pragma unroll
    for (int j = 0; j < 16; j++) acc[i][j] = 0.f;

  for (int s = 0; s < 8; s++) {
    #pragma unroll
    for (int j = 0; j < 32; j++) {
      int i = tid + j*256;
      int k = i >> 8, o = i & 255;
      sW[k*320 + (o>>4)*20 + (o&15)] = wbuf[j];
    }
    __syncthreads();
    if (s < 7) {
      #pragma unroll
      for (int j = 0; j < 32; j++) {
        int i = tid + j*256;
        int k = i >> 8, o = i & 255;
        wbuf[j] = proj_w[(size_t)((s+1)*32 + k)*DOUTV + o];
      }
    }
    const float* xb = sX + lt*4*260 + s*32;
    #pragma unroll 2
    for (int k = 0; k < 32; k++) {
      float xr[4];
      #pragma unroll
      for (int i = 0; i < 4; i++) xr[i] = xb[i*260 + k];
      const float* wrow = sW + k*320 + ot*20;
      float4 w0 = *(const float4*)&wrow[0];
      float4 w1 = *(const float4*)&wrow[4];
      float4 w2 = *(const float4*)&wrow[8];
      float4 w3 = *(const float4*)&wrow[12];
      float wr[16] = {w0.x,w0.y,w0.z,w0.w, w1.x,w1.y,w1.z,w1.w,
                      w2.x,w2.y,w2.z,w2.w, w3.x,w3.y,w3.z,w3.w};
      #pragma unroll
      for (int i = 0; i < 4; i++)
        #pragma unroll
        for (int j = 0; j < 16; j++) acc[i][j] += xr[i]*wr[j];
    }
    __syncthreads();
  }

  #pragma unroll
  for (int j = 0; j < 16; j++) {
    int O = ot*16 + j;
    float bb = proj_b[O];
    float4 ov = make_float4(acc[0][j]+bb, acc[1][j]+bb, acc[2][j]+bb, acc[3][j]+bb);
    *(float4*)&out[((size_t)(b*DOUTV + O))*LSEQ + l0 + lt*4] = ov;
  }
}

extern "C" void kernel_launch(void* const* d_in, const int* in_sizes, int n_in,
                              void* d_out, int out_size) {
  const float* x        = (const float*)d_in[0];
  const float* ln_w     = (const float*)d_in[1];
  const float* ln_b     = (const float*)d_in[2];
  const float* skip_s   = (const float*)d_in[3];
  const float* proj_w   = (const float*)d_in[4];
  const float* proj_b   = (const float*)d_in[5];
  const float* W_in     = (const float*)d_in[6];
  const float* conv_w   = (const float*)d_in[7];
  const float* conv_b   = (const float*)d_in[8];
  const float* dt_bias  = (const float*)d_in[9];
  const float* A_log    = (const float*)d_in[10];
  const float* Dp       = (const float*)d_in[11];
  const float* rms_w    = (const float*)d_in[12];
  const float* W_out    = (const float*)d_in[13];
  float* out = (float*)d_out;

  cudaFuncSetAttribute(k2_chunk, cudaFuncAttributeMaxDynamicSharedMemorySize, SM2_BYTES);
  cudaFuncSetAttribute(k4_tail,  cudaFuncAttributeMaxDynamicSharedMemorySize, SM4_BYTES);
  cudaFuncSetAttribute(k5_out,   cudaFuncAttributeMaxDynamicSharedMemorySize, SM5_BYTES);

  k1_ln_split<<<dim3(96, 8), 256>>>(x, ln_w, ln_b, 0);
  k1_ln_split<<<dim3(96, 8), 256>>>(x, ln_w, ln_b, 96);
  k1_ln_split<<<dim3(96, 8), 256>>>(x, ln_w, ln_b, 192);
  k2_chunk<<<dim3(NCHUNKV, NSEQV), 256, SM2_BYTES>>>(W_in, conv_w, conv_b, dt_bias, A_log, Dp);
  k3_scan<<<512, 128>>>();
  k4_tail<<<dim3(144, NSEQV), 256, SM4_BYTES>>>(rms_w, W_out, skip_s);
  k5_out<<<dim3(144, 8), 256, SM5_BYTES>>>(ln_w, ln_b, proj_w, proj_b, out);
}

// round 15
// speedup vs baseline: 1.1122x; 1.1122x over previous
#include <cuda_runtime.h>
#include <math.h>

#define B0V      8
#define CINV     256
#define LSEQ     9216
#define DMV      32
#define DINV     64
#define DSTATEV  64
#define NHV      8
#define HDV      8
#define CONVCH   192
#define DPROJ    264
#define CHUNKV   32
#define NCHUNKV  288
#define NSEQV    64
#define DOUTV    256

// ---------------- scratch ----------------
__device__ float g_xs[(size_t)NSEQV*LSEQ*DMV];
__device__ float g_y0[(size_t)NSEQV*LSEQ*DINV];
__device__ float g_Cm[(size_t)NSEQV*LSEQ*DSTATEV];
__device__ float g_zs[(size_t)NSEQV*LSEQ*DINV];
__device__ float g_ea[(size_t)NSEQV*LSEQ*NHV];
__device__ float g_st[(size_t)NSEQV*NCHUNKV*NHV*HDV*DSTATEV];
__device__ float g_cd[(size_t)NSEQV*NCHUNKV*NHV];
__device__ float g_ym[(size_t)B0V*LSEQ*CINV];

__device__ __forceinline__ float siluf(float v) { return v / (1.f + __expf(-v)); }

// ============ k1: LN over C + split-transpose ============
// launched as 3 slices of grid (96, 8) with xoff = 0/96/192 (profiler phase shift)
__global__ __launch_bounds__(256) void k1_ln_split(
    const float* __restrict__ x, const float* __restrict__ lw,
    const float* __restrict__ lb, int xoff) {
  __shared__ float tile[256*33];
  __shared__ float s_mu[32], s_rs[32];
  int b = blockIdx.y;
  int l0 = (blockIdx.x + xoff) * 32;
  int tid = threadIdx.x;

  for (int i = tid; i < 256*32; i += 256) {
    int c = i >> 5, l = i & 31;
    tile[c*33 + l] = x[((size_t)(b*CINV + c))*LSEQ + l0 + l];
  }
  __syncthreads();
  {
    int w = tid >> 5, lane = tid & 31;
    for (int q = 0; q < 4; q++) {
      int l = w*4 + q;
      float s = 0.f, ss = 0.f;
      #pragma unroll
      for (int j = 0; j < 8; j++) {
        float v = tile[(lane + 32*j)*33 + l];
        s += v; ss += v*v;
      }
      #pragma unroll
      for (int o = 16; o > 0; o >>= 1) {
        s  += __shfl_xor_sync(0xffffffffu, s,  o);
        ss += __shfl_xor_sync(0xffffffffu, ss, o);
      }
      if (lane == 0) {
        float mu = s * (1.f/256.f);
        float var = ss * (1.f/256.f) - mu*mu;
        s_mu[l] = mu;
        s_rs[l] = rsqrtf(var + 1e-5f);
      }
    }
  }
  __syncthreads();
  for (int i = tid; i < 256*32; i += 256) {
    int cg = i >> 10;
    int l  = (i >> 5) & 31;
    int j  = i & 31;
    int c  = cg*32 + j;
    float v = (tile[c*33 + l] - s_mu[l]) * s_rs[l] * lw[c] + lb[c];
    int seq = cg*B0V + b;
    g_xs[((size_t)seq*LSEQ + l0 + l)*DMV + j] = v;
  }
}

// ============ k2: in_proj + conv + intra-chunk SSD ============
// smem 12944 floats = 51.8KB -> 4 blocks/SM.
// phase-A: sXT[32][36]@0, sWs[32][88]@1152, sZX[34][264]@3968
// phase-B: sDT@0, sAC@256, sED@520, sE1@776,
//          sXH@1152, sB@3200, sC[32][68]@5248, sXDT@7424, sG@9472, sCF[32][68]@10528
#define SM2_FLOATS 12944
#define SM2_BYTES (SM2_FLOATS * 4)
#define ZXB 3968

__global__ __launch_bounds__(256, 4) void k2_chunk(
    const float* __restrict__ W_in, const float* __restrict__ conv_w,
    const float* __restrict__ conv_b, const float* __restrict__ dt_bias,
    const float* __restrict__ A_log, const float* __restrict__ Dp) {
  extern __shared__ float sm[];
  float* sXT  = sm;             // [32][36]
  float* sWs  = sm + 1152;      // [32][88]
  float* sZX  = sm + ZXB;       // [34][264]
  // phase-B aliases
  float* sDT  = sm;             // [32][8]
  float* sAC  = sm + 256;       // [8][33]
  float* sED  = sm + 520;      // [8][32]
  float* sE1  = sm + 776;      // [8][32]
  float* sXH  = sm + 1152;     // [32][64]
  float* sB   = sm + 3200;     // [32][64]
  float* sC   = sm + 5248;     // [32][68]
  float* sXDT = sm + 7424;     // [32][64]
  float* sG   = sm + 9472;     // [32][33]
  float* sCF  = sm + 10528;    // [32][68]

  int chunk = blockIdx.x;
  int seq   = blockIdx.y;
  int c0 = chunk * CHUNKV;
  int tid = threadIdx.x;

  // prefetch W slab 0 into regs
  float wreg[11];
  #pragma unroll
  for (int j = 0; j < 11; j++) {
    int i = tid + j*256;
    int k = i / 88, col = i - k*88;
    wreg[j] = W_in[k*DPROJ + col];
  }

  // load x^T tile
  for (int i = tid; i < 36*32; i += 256) {
    int r = i >> 5, k = i & 31;
    int l = c0 - 2 + r;
    float v = 0.f;
    if (r < 34 && l >= 0) v = g_xs[((size_t)seq*LSEQ + l)*DMV + k];
    sXT[k*36 + r] = v;
  }
  __syncthreads();

  // in_proj GEMM in 3 slabs, 4r x 4n tiles, 198 active threads (R13 config),
  // reg double-buffered W
  for (int s = 0; s < 3; s++) {
    int gbase = s*88;
    #pragma unroll
    for (int j = 0; j < 11; j++) sWs[tid + j*256] = wreg[j];
    __syncthreads();
    if (s < 2) {
      int gnext = gbase + 88;
      #pragma unroll
      for (int j = 0; j < 11; j++) {
        int i = tid + j*256;
        int k = i / 88, col = i - k*88;
        wreg[j] = W_in[k*DPROJ + gnext + col];
      }
    }
    if (tid < 198) {
      int rt = tid / 22, ct = tid - rt*22;
      int r0 = rt*4, n0 = ct*4;
      float acc[4][4];
      #pragma unroll
      for (int i = 0; i < 4; i++)
        #pragma unroll
        for (int j = 0; j < 4; j++) acc[i][j] = 0.f;
      #pragma unroll 4
      for (int k = 0; k < 32; k++) {
        float4 xv = *(const float4*)&sXT[k*36 + r0];
        float4 wv = *(const float4*)&sWs[k*88 + n0];
        float xr[4] = {xv.x, xv.y, xv.z, xv.w};
        float wr[4] = {wv.x, wv.y, wv.z, wv.w};
        #pragma unroll
        for (int i = 0; i < 4; i++)
          #pragma unroll
          for (int j = 0; j < 4; j++) acc[i][j] += xr[i]*wr[j];
      }
      #pragma unroll
      for (int i = 0; i < 4; i++) {
        int r = r0 + i;
        if (r < 34)
          *(float4*)&sZX[r*DPROJ + gbase + n0] =
            make_float4(acc[i][0],acc[i][1],acc[i][2],acc[i][3]);
      }
    }
    __syncthreads();
  }

  // conv(3)+silu into registers; z and dt in the same phase
  float creg[24];
  #pragma unroll
  for (int j = 0; j < 24; j++) {
    int i = j*256 + tid;
    int l = i / CONVCH, c = i - l*CONVCH;
    float v = conv_w[c*3+0]*sZX[ l   *DPROJ + 64 + c]
            + conv_w[c*3+1]*sZX[(l+1)*DPROJ + 64 + c]
            + conv_w[c*3+2]*sZX[(l+2)*DPROJ + 64 + c]
            + conv_b[c];
    v = siluf(v);
    creg[j] = v;
    if (c >= 128)
      g_Cm[((size_t)seq*LSEQ + c0 + l)*DSTATEV + (c-128)] = v;
  }
  for (int i = tid; i < 32*64; i += 256) {
    int l = i >> 6, j = i & 63;
    g_zs[((size_t)seq*LSEQ + c0 + l)*DINV + j] = siluf(sZX[(l+2)*DPROJ + j]);
  }
  {
    int l = tid >> 3, h = tid & 7;
    float raw = sZX[(l+2)*DPROJ + 256 + h] + dt_bias[h];
    sDT[l*8 + h] = (raw > 20.f) ? raw : log1pf(__expf(raw));
  }
  __syncthreads();

  // scatter conv outputs (ZX/W regions now dead)
  #pragma unroll
  for (int j = 0; j < 24; j++) {
    int i = j*256 + tid;
    int l = i / CONVCH, c = i - l*CONVCH;
    if (c < 64)       sXH[l*64 + c] = creg[j];
    else if (c < 128) sB[l*64 + (c-64)] = creg[j];
    else              sC[l*68 + (c-128)] = creg[j];
  }
  // per-head inclusive scan via warp shuffles
  {
    int w = tid >> 5, lane = tid & 31;
    float Ah = -__expf(A_log[w]);
    float dt = sDT[lane*8 + w];
    float a  = dt * Ah;
    float e1 = __expf(a);
    #pragma unroll
    for (int o = 1; o < 32; o <<= 1) {
      float v = __shfl_up_sync(0xffffffffu, a, o);
      if (lane >= o) a += v;
    }
    sAC[w*33 + lane] = a;
    float alast = __shfl_sync(0xffffffffu, a, 31);
    sED[w*32 + lane] = __expf(alast - a);
    sE1[w*32 + lane] = e1;
    if (lane == 31) g_cd[((size_t)seq*NCHUNKV + chunk)*NHV + w] = __expf(a);
  }
  __syncthreads();

  // Merged phase: XDT + CF + g_ea + G (G reads sB/sC valid since previous
  // barrier; writes sG, disjoint from sXDT/sCF)
  for (int i = tid; i < 32*64; i += 256) {
    int l = i >> 6, d = i & 63;
    float v = sXH[l*64+d]*sDT[l*8 + (d>>3)];
    sXDT[l*64+d] = v;
    sCF[l*68+d]  = v * sED[(d>>3)*32 + l];
  }
  {
    int l = tid >> 3, h = tid & 7;
    g_ea[((size_t)seq*LSEQ + c0 + l)*NHV + h] = __expf(sAC[h*33+l]);
  }
  {
    int w = tid >> 5, l = tid & 31;
    float a0=0.f,a1=0.f,a2=0.f,a3=0.f;
    int s0=w, s1=w+8, s2=w+16, s3=w+24;
    #pragma unroll 4
    for (int n4 = 0; n4 < 64; n4 += 4) {
      float4 cv = *(const float4*)&sC[l*68+n4];
      float4 b0 = *(const float4*)&sB[s0*64+n4];
      float4 b1 = *(const float4*)&sB[s1*64+n4];
      float4 b2 = *(const float4*)&sB[s2*64+n4];
      float4 b3 = *(const float4*)&sB[s3*64+n4];
      a0 += cv.x*b0.x + cv.y*b0.y + cv.z*b0.z + cv.w*b0.w;
      a1 += cv.x*b1.x + cv.y*b1.y + cv.z*b1.z + cv.w*b1.w;
      a2 += cv.x*b2.x + cv.y*b2.y + cv.z*b2.z + cv.w*b2.w;
      a3 += cv.x*b3.x + cv.y*b3.y + cv.z*b3.z + cv.w*b3.w;
    }
    sG[l*33+s0]=a0; sG[l*33+s1]=a1; sG[l*33+s2]=a2; sG[l*33+s3]=a3;
  }
  __syncthreads();

  // chunk states as 4hp x 4n GEMM over sCF/sB
  {
    int nt = tid & 15, ht = tid >> 4;
    int n0 = nt*4, hp0 = ht*4;
    float acc[4][4];
    #pragma unroll
    for (int i = 0; i < 4; i++)
      #pragma unroll
      for (int j = 0; j < 4; j++) acc[i][j] = 0.f;
    #pragma unroll 4
    for (int l = 0; l < 32; l++) {
      float4 cf = *(const float4*)&sCF[l*68 + hp0];
      float4 bv = *(const float4*)&sB[l*64 + n0];
      float cr[4] = {cf.x, cf.y, cf.z, cf.w};
      float br[4] = {bv.x, bv.y, bv.z, bv.w};
      #pragma unroll
      for (int i = 0; i < 4; i++)
        #pragma unroll
        for (int j = 0; j < 4; j++) acc[i][j] += cr[i]*br[j];
    }
    size_t sbase = (((size_t)seq*NCHUNKV + chunk)*NHV)*(HDV*DSTATEV);
    #pragma unroll
    for (int i = 0; i < 4; i++)
      *(float4*)&g_st[sbase + (size_t)(hp0+i)*64 + n0] =
        make_float4(acc[i][0],acc[i][1],acc[i][2],acc[i][3]);
  }

  // Yd + D term: decay as running product
  {
    int l = tid >> 3, h = tid & 7;
    float acc[8];
    #pragma unroll
    for (int p = 0; p < 8; p++) acc[p] = Dp[h]*sXH[l*64 + h*8 + p];
    const float* e1 = sE1 + h*32;
    float w = 1.f;
    for (int s = l; s >= 0; s--) {
      float wgt = sG[l*33+s] * w;
      float4 xa = *(const float4*)&sXDT[s*64 + h*8];
      float4 xb = *(const float4*)&sXDT[s*64 + h*8 + 4];
      acc[0]+=wgt*xa.x; acc[1]+=wgt*xa.y; acc[2]+=wgt*xa.z; acc[3]+=wgt*xa.w;
      acc[4]+=wgt*xb.x; acc[5]+=wgt*xb.y; acc[6]+=wgt*xb.z; acc[7]+=wgt*xb.w;
      w *= e1[s];
    }
    size_t ob = ((size_t)seq*LSEQ + c0 + l)*DINV + h*8;
    *(float4*)&g_y0[ob]   = make_float4(acc[0],acc[1],acc[2],acc[3]);
    *(float4*)&g_y0[ob+4] = make_float4(acc[4],acc[5],acc[6],acc[7]);
  }
}

// ============ k3: inter-chunk scan (states -> prev, in place) ============
__global__ __launch_bounds__(128) void k3_scan() {
  int bid = blockIdx.x;
  int seq = bid >> 3, h = bid & 7;
  int e = threadIdx.x * 4;
  size_t base = (((size_t)seq*NCHUNKV)*NHV + h)*(HDV*DSTATEV) + e;
  size_t cdb  = (size_t)seq*NCHUNKV*NHV + h;
  const size_t CS = (size_t)NHV*HDV*DSTATEV;
  float4 carry = make_float4(0.f,0.f,0.f,0.f);
  for (int c = 0; c < NCHUNKV; c += 4) {
    float4 s0 = *(float4*)&g_st[base];
    float4 s1 = *(float4*)&g_st[base + CS];
    float4 s2 = *(float4*)&g_st[base + 2*CS];
    float4 s3 = *(float4*)&g_st[base + 3*CS];
    float d0 = g_cd[cdb], d1 = g_cd[cdb+8], d2 = g_cd[cdb+16], d3 = g_cd[cdb+24];
    *(float4*)&g_st[base] = carry;
    carry.x = carry.x*d0 + s0.x; carry.y = carry.y*d0 + s0.y;
    carry.z = carry.z*d0 + s0.z; carry.w = carry.w*d0 + s0.w;
    *(float4*)&g_st[base + CS] = carry;
    carry.x = carry.x*d1 + s1.x; carry.y = carry.y*d1 + s1.y;
    carry.z = carry.z*d1 + s1.z; carry.w = carry.w*d1 + s1.w;
    *(float4*)&g_st[base + 2*CS] = carry;
    carry.x = carry.x*d2 + s2.x; carry.y = carry.y*d2 + s2.y;
    carry.z = carry.z*d2 + s2.z; carry.w = carry.w*d2 + s2.w;
    *(float4*)&g_st[base + 3*CS] = carry;
    carry.x = carry.x*d3 + s3.x; carry.y = carry.y*d3 + s3.y;
    carry.z = carry.z*d3 + s3.z; carry.w = carry.w*d3 + s3.w;
    base += 4*CS; cdb += 32;
  }
}

// ============ k4: two chunks/block, phase-aliased smem (52KB, 4 blocks/SM) ====
#define SM4_FLOATS 12992
#define SM4_BYTES (SM4_FLOATS * 4)
__global__ __launch_bounds__(256, 4) void k4_tail(
    const float* __restrict__ rms_w, const float* __restrict__ W_out,
    const float* __restrict__ skip_scale) {
  extern __shared__ float s4[];
  float* sPrev = s4;            // ch*4352 + n*68 + hp
  float* sC    = s4 + 8704;     // l*66 + n
  float* sY    = s4;            // l*68 + hp   (phase 2)
  float* sWo   = s4 + 8704;     // d*32 + m    (phase 2)
  float* sRS   = s4 + 12928;    // [64]
  int cp = blockIdx.x, seq = blockIdx.y;
  int c0 = cp * 64;
  int tid = threadIdx.x;
  float skip = skip_scale[0];

  {
    size_t stb = (((size_t)seq*NCHUNKV + cp*2)*NHV)*(HDV*DSTATEV);
    for (int i = tid; i < 8192; i += 256) {
      int ch = i >> 12, r = i & 4095;
      int hp = r >> 6, n = r & 63;
      sPrev[ch*4352 + n*68 + hp] = g_st[stb + (size_t)ch*4096 + (size_t)hp*64 + n];
    }
  }
  for (int i = tid; i < 4096; i += 256) {
    int l = i >> 6, n = i & 63;
    sC[l*66+n] = g_Cm[((size_t)seq*LSEQ + c0 + l)*DSTATEV + n];
  }
  __syncthreads();

  float yv[4][4];
  int ht = tid & 15, lt = tid >> 4;
  int l0g = lt*4, hp0 = ht*4;
  {
    int ch = lt >> 3;
    const float* Cb = sC + l0g*66;
    const float* Pb = sPrev + ch*4352 + hp0;
    float acc[4][4];
    #pragma unroll
    for (int i = 0; i < 4; i++)
      #pragma unroll
      for (int j = 0; j < 4; j++) acc[i][j] = 0.f;
    #pragma unroll 4
    for (int n = 0; n < 64; n++) {
      float4 pv = *(const float4*)&Pb[n*68];
      float c0v = Cb[n], c1v = Cb[66+n], c2v = Cb[132+n], c3v = Cb[198+n];
      acc[0][0]+=c0v*pv.x; acc[0][1]+=c0v*pv.y; acc[0][2]+=c0v*pv.z; acc[0][3]+=c0v*pv.w;
      acc[1][0]+=c1v*pv.x; acc[1][1]+=c1v*pv.y; acc[1][2]+=c1v*pv.z; acc[1][3]+=c1v*pv.w;
      acc[2][0]+=c2v*pv.x; acc[2][1]+=c2v*pv.y; acc[2][2]+=c2v*pv.z; acc[2][3]+=c2v*pv.w;
      acc[3][0]+=c3v*pv.x; acc[3][1]+=c3v*pv.y; acc[3][2]+=c3v*pv.z; acc[3][3]+=c3v*pv.w;
    }
    int h = hp0 >> 3;
    #pragma unroll
    for (int i = 0; i < 4; i++) {
      int l = l0g + i;
      size_t row = (size_t)seq*LSEQ + c0 + l;
      float ea = g_ea[row*NHV + h];
      float4 y0 = *(const float4*)&g_y0[row*DINV + hp0];
      float4 zz = *(const float4*)&g_zs[row*DINV + hp0];
      yv[i][0] = (y0.x + ea*acc[i][0])*zz.x;
      yv[i][1] = (y0.y + ea*acc[i][1])*zz.y;
      yv[i][2] = (y0.z + ea*acc[i][2])*zz.z;
      yv[i][3] = (y0.w + ea*acc[i][3])*zz.w;
    }
  }
  __syncthreads();
  #pragma unroll
  for (int i = 0; i < 4; i++)
    *(float4*)&sY[(l0g+i)*68 + hp0] = make_float4(yv[i][0],yv[i][1],yv[i][2],yv[i][3]);
  for (int i = tid; i < 2048; i += 256) sWo[i] = W_out[i];
  __syncthreads();

  {
    int w = tid >> 5, lane = tid & 31;
    for (int q = 0; q < 8; q++) {
      int l = w*8 + q;
      float v1 = sY[l*68 + lane], v2 = sY[l*68 + lane + 32];
      float ss = v1*v1 + v2*v2;
      #pragma unroll
      for (int o = 16; o > 0; o >>= 1) ss += __shfl_xor_sync(0xffffffffu, ss, o);
      if (lane == 0) sRS[l] = rsqrtf(ss*(1.f/64.f) + 1e-5f);
    }
  }
  __syncthreads();
  for (int i = tid; i < 4096; i += 256) {
    int l = i >> 6, d = i & 63;
    sY[l*68+d] *= sRS[l]*rms_w[d];
  }
  __syncthreads();
  {
    int mt = tid & 15, lt2 = tid >> 4;
    int l0 = lt2*4, m0 = mt*2;
    float acc[4][2];
    #pragma unroll
    for (int i = 0; i < 4; i++) { acc[i][0] = 0.f; acc[i][1] = 0.f; }
    const float* Yb = sY + l0*68;
    #pragma unroll 4
    for (int d = 0; d < 64; d++) {
      float2 wv = *(const float2*)&sWo[d*32 + m0];
      float y0v = Yb[d], y1v = Yb[68+d], y2v = Yb[136+d], y3v = Yb[204+d];
      acc[0][0]+=y0v*wv.x; acc[0][1]+=y0v*wv.y;
      acc[1][0]+=y1v*wv.x; acc[1][1]+=y1v*wv.y;
      acc[2][0]+=y2v*wv.x; acc[2][1]+=y2v*wv.y;
      acc[3][0]+=y3v*wv.x; acc[3][1]+=y3v*wv.y;
    }
    int split = seq >> 3, b = seq & 7;
    #pragma unroll
    for (int i = 0; i < 4; i++) {
      int l = l0 + i;
      float2 xk = *(const float2*)&g_xs[((size_t)seq*LSEQ + c0 + l)*DMV + m0];
      float2 ov;
      ov.x = acc[i][0] + skip*xk.x;
      ov.y = acc[i][1] + skip*xk.y;
      *(float2*)&g_ym[((size_t)b*LSEQ + c0 + l)*CINV + split*32 + m0] = ov;
    }
  }
}

// ============ k5: LN + 256x256 projection, reg-double-buffered W slabs ====
#define SM5_FLOATS 26880
#define SM5_BYTES (SM5_FLOATS * 4)
__global__ __launch_bounds__(256, 2) void k5_out(
    const float* __restrict__ lw, const float* __restrict__ lb,
    const float* __restrict__ proj_w, const float* __restrict__ proj_b,
    float* __restrict__ out) {
  extern __shared__ float sm[];
  float* sX = sm;           // [64][260]
  float* sW = sm + 16640;   // [32][320] swizzled: addr = k*320 + (o>>4)*20 + (o&15)
  int b = blockIdx.y;
  int l0 = blockIdx.x * 64;
  int tid = threadIdx.x;

  float wbuf[32];
  #pragma unroll
  for (int j = 0; j < 32; j++) {
    int i = tid + j*256;
    int k = i >> 8, o = i & 255;
    wbuf[j] = proj_w[(size_t)k*DOUTV + o];
  }

  for (int i = tid; i < 64*256; i += 256) {
    int l = i >> 8, c = i & 255;
    sX[l*260 + c] = g_ym[((size_t)b*LSEQ + l0 + l)*CINV + c];
  }
  __syncthreads();
  {
    int w = tid >> 5, lane = tid & 31;
    for (int q = 0; q < 8; q++) {
      int l = w*8 + q;
      float s = 0.f, ss = 0.f;
      #pragma unroll
      for (int j = 0; j < 8; j++) {
        float v = sX[l*260 + lane + 32*j];
        s += v; ss += v*v;
      }
      #pragma unroll
      for (int o = 16; o > 0; o >>= 1) {
        s  += __shfl_xor_sync(0xffffffffu, s,  o);
        ss += __shfl_xor_sync(0xffffffffu, ss, o);
      }
      float mu = s * (1.f/256.f);
      float rs = rsqrtf(ss*(1.f/256.f) - mu*mu + 1e-5f);
      #pragma unroll
      for (int j = 0; j < 8; j++) {
        int c = lane + 32*j;
        sX[l*260 + c] = (sX[l*260 + c] - mu)*rs*lw[c] + lb[c];
      }
    }
  }
  __syncthreads();

  int ot = tid & 15, lt = tid >> 4;
  float acc[4][16];
  #pragma unroll
  for (int i = 0; i < 4; i++)
    #pragma unroll
    for (int j = 0; j < 16; j++) acc[i][j] = 0.f;

  for (int s = 0; s < 8; s++) {
    #pragma unroll
    for (int j = 0; j < 32; j++) {
      int i = tid + j*256;
      int k = i >> 8, o = i & 255;
      sW[k*320 + (o>>4)*20 + (o&15)] = wbuf[j];
    }
    __syncthreads();
    if (s < 7) {
      #pragma unroll
      for (int j = 0; j < 32; j++) {
        int i = tid + j*256;
        int k = i >> 8, o = i & 255;
        wbuf[j] = proj_w[(size_t)((s+1)*32 + k)*DOUTV + o];
      }
    }
    const float* xb = sX + lt*4*260 + s*32;
    #pragma unroll 2
    for (int k = 0; k < 32; k++) {
      float xr[4];
      #pragma unroll
      for (int i = 0; i < 4; i++) xr[i] = xb[i*260 + k];
      const float* wrow = sW + k*320 + ot*20;
      float4 w0 = *(const float4*)&wrow[0];
      float4 w1 = *(const float4*)&wrow[4];
      float4 w2 = *(const float4*)&wrow[8];
      float4 w3 = *(const float4*)&wrow[12];
      float wr[16] = {w0.x,w0.y,w0.z,w0.w, w1.x,w1.y,w1.z,w1.w,
                      w2.x,w2.y,w2.z,w2.w, w3.x,w3.y,w3.z,w3.w};
      #pragma unroll
      for (int i = 0; i < 4; i++)
        #pragma unroll
        for (int j = 0; j < 16; j++) acc[i][j] += xr[i]*wr[j];
    }
    __syncthreads();
  }

  #pragma unroll
  for (int j = 0; j < 16; j++) {
    int O = ot*16 + j;
    float bb = proj_b[O];
    float4 ov = make_float4(acc[0][j]+bb, acc[1][j]+bb, acc[2][j]+bb, acc[3][j]+bb);
    *(float4*)&out[((size_t)(b*DOUTV + O))*LSEQ + l0 + lt*4] = ov;
  }
}

extern "C" void kernel_launch(void* const* d_in, const int* in_sizes, int n_in,
                              void* d_out, int out_size) {
  const float* x        = (const float*)d_in[0];
  const float* ln_w     = (const float*)d_in[1];
  const float* ln_b     = (const float*)d_in[2];
  const float* skip_s   = (const float*)d_in[3];
  const float* proj_w   = (const float*)d_in[4];
  const float* proj_b   = (const float*)d_in[5];
  const float* W_in     = (const float*)d_in[6];
  const float* conv_w   = (const float*)d_in[7];
  const float* conv_b   = (const float*)d_in[8];
  const float* dt_bias  = (const float*)d_in[9];
  const float* A_log    = (const float*)d_in[10];
  const float* Dp       = (const float*)d_in[11];
  const float* rms_w    = (const float*)d_in[12];
  const float* W_out    = (const float*)d_in[13];
  float* out = (float*)d_out;

  cudaFuncSetAttribute(k2_chunk, cudaFuncAttributeMaxDynamicSharedMemorySize, SM2_BYTES);
  cudaFuncSetAttribute(k4_tail,  cudaFuncAttributeMaxDynamicSharedMemorySize, SM4_BYTES);
  cudaFuncSetAttribute(k5_out,   cudaFuncAttributeMaxDynamicSharedMemorySize, SM5_BYTES);

  k1_ln_split<<<dim3(96, 8), 256>>>(x, ln_w, ln_b, 0);
  k1_ln_split<<<dim3(96, 8), 256>>>(x, ln_w, ln_b, 96);
  k1_ln_split<<<dim3(96, 8), 256>>>(x, ln_w, ln_b, 192);
  k2_chunk<<<dim3(NCHUNKV, NSEQV), 256, SM2_BYTES>>>(W_in, conv_w, conv_b, dt_bias, A_log, Dp);
  k3_scan<<<512, 128>>>();
  k4_tail<<<dim3(144, NSEQV), 256, SM4_BYTES>>>(rms_w, W_out, skip_s);
  k5_out<<<dim3(144, 8), 256, SM5_BYTES>>>(ln_w, ln_b, proj_w, proj_b, out);
}

// round 16
// speedup vs baseline: 1.1226x; 1.0094x over previous
#include <cuda_runtime.h>
#include <math.h>

#define B0V      8
#define CINV     256
#define LSEQ     9216
#define DMV      32
#define DINV     64
#define DSTATEV  64
#define NHV      8
#define HDV      8
#define CONVCH   192
#define DPROJ    264
#define CHUNKV   32
#define NCHUNKV  288
#define NSEQV    64
#define DOUTV    256

// ---------------- scratch ----------------
__device__ float g_xs[(size_t)NSEQV*LSEQ*DMV];
__device__ float g_y0[(size_t)NSEQV*LSEQ*DINV];
__device__ float g_Cm[(size_t)NSEQV*LSEQ*DSTATEV];
__device__ float g_zs[(size_t)NSEQV*LSEQ*DINV];
__device__ float g_ea[(size_t)NSEQV*LSEQ*NHV];
__device__ float g_st[(size_t)NSEQV*NCHUNKV*NHV*HDV*DSTATEV];
__device__ float g_cd[(size_t)NSEQV*NCHUNKV*NHV];
__device__ float g_ym[(size_t)B0V*LSEQ*CINV];

__device__ __forceinline__ float siluf(float v) { return v / (1.f + __expf(-v)); }

// ============ k1: LN over C + split-transpose ============
// grid (288, 8), 256 threads
__global__ __launch_bounds__(256) void k1_ln_split(
    const float* __restrict__ x, const float* __restrict__ lw,
    const float* __restrict__ lb) {
  __shared__ float tile[256*33];
  __shared__ float s_mu[32], s_rs[32];
  int b = blockIdx.y;
  int l0 = blockIdx.x * 32;
  int tid = threadIdx.x;

  for (int i = tid; i < 256*32; i += 256) {
    int c = i >> 5, l = i & 31;
    tile[c*33 + l] = x[((size_t)(b*CINV + c))*LSEQ + l0 + l];
  }
  __syncthreads();
  {
    int w = tid >> 5, lane = tid & 31;
    for (int q = 0; q < 4; q++) {
      int l = w*4 + q;
      float s = 0.f, ss = 0.f;
      #pragma unroll
      for (int j = 0; j < 8; j++) {
        float v = tile[(lane + 32*j)*33 + l];
        s += v; ss += v*v;
      }
      #pragma unroll
      for (int o = 16; o > 0; o >>= 1) {
        s  += __shfl_xor_sync(0xffffffffu, s,  o);
        ss += __shfl_xor_sync(0xffffffffu, ss, o);
      }
      if (lane == 0) {
        float mu = s * (1.f/256.f);
        float var = ss * (1.f/256.f) - mu*mu;
        s_mu[l] = mu;
        s_rs[l] = rsqrtf(var + 1e-5f);
      }
    }
  }
  __syncthreads();
  for (int i = tid; i < 256*32; i += 256) {
    int cg = i >> 10;
    int l  = (i >> 5) & 31;
    int j  = i & 31;
    int c  = cg*32 + j;
    float v = (tile[c*33 + l] - s_mu[l]) * s_rs[l] * lw[c] + lb[c];
    int seq = cg*B0V + b;
    g_xs[((size_t)seq*LSEQ + l0 + l)*DMV + j] = v;
  }
}

// ============ k2: in_proj + conv + intra-chunk SSD (R15 validated config) ====
#define SM2_FLOATS 12944
#define SM2_BYTES (SM2_FLOATS * 4)
#define ZXB 3968

__global__ __launch_bounds__(256, 4) void k2_chunk(
    const float* __restrict__ W_in, const float* __restrict__ conv_w,
    const float* __restrict__ conv_b, const float* __restrict__ dt_bias,
    const float* __restrict__ A_log, const float* __restrict__ Dp) {
  extern __shared__ float sm[];
  float* sXT  = sm;             // [32][36]
  float* sWs  = sm + 1152;      // [32][88]
  float* sZX  = sm + ZXB;       // [34][264]
  // phase-B aliases
  float* sDT  = sm;             // [32][8]
  float* sAC  = sm + 256;       // [8][33]
  float* sED  = sm + 520;      // [8][32]
  float* sE1  = sm + 776;      // [8][32]
  float* sXH  = sm + 1152;     // [32][64]
  float* sB   = sm + 3200;     // [32][64]
  float* sC   = sm + 5248;     // [32][68]
  float* sXDT = sm + 7424;     // [32][64]
  float* sG   = sm + 9472;     // [32][33]
  float* sCF  = sm + 10528;    // [32][68]

  int chunk = blockIdx.x;
  int seq   = blockIdx.y;
  int c0 = chunk * CHUNKV;
  int tid = threadIdx.x;

  float wreg[11];
  #pragma unroll
  for (int j = 0; j < 11; j++) {
    int i = tid + j*256;
    int k = i / 88, col = i - k*88;
    wreg[j] = W_in[k*DPROJ + col];
  }

  for (int i = tid; i < 36*32; i += 256) {
    int r = i >> 5, k = i & 31;
    int l = c0 - 2 + r;
    float v = 0.f;
    if (r < 34 && l >= 0) v = g_xs[((size_t)seq*LSEQ + l)*DMV + k];
    sXT[k*36 + r] = v;
  }
  __syncthreads();

  for (int s = 0; s < 3; s++) {
    int gbase = s*88;
    #pragma unroll
    for (int j = 0; j < 11; j++) sWs[tid + j*256] = wreg[j];
    __syncthreads();
    if (s < 2) {
      int gnext = gbase + 88;
      #pragma unroll
      for (int j = 0; j < 11; j++) {
        int i = tid + j*256;
        int k = i / 88, col = i - k*88;
        wreg[j] = W_in[k*DPROJ + gnext + col];
      }
    }
    if (tid < 198) {
      int rt = tid / 22, ct = tid - rt*22;
      int r0 = rt*4, n0 = ct*4;
      float acc[4][4];
      #pragma unroll
      for (int i = 0; i < 4; i++)
        #pragma unroll
        for (int j = 0; j < 4; j++) acc[i][j] = 0.f;
      #pragma unroll 4
      for (int k = 0; k < 32; k++) {
        float4 xv = *(const float4*)&sXT[k*36 + r0];
        float4 wv = *(const float4*)&sWs[k*88 + n0];
        float xr[4] = {xv.x, xv.y, xv.z, xv.w};
        float wr[4] = {wv.x, wv.y, wv.z, wv.w};
        #pragma unroll
        for (int i = 0; i < 4; i++)
          #pragma unroll
          for (int j = 0; j < 4; j++) acc[i][j] += xr[i]*wr[j];
      }
      #pragma unroll
      for (int i = 0; i < 4; i++) {
        int r = r0 + i;
        if (r < 34)
          *(float4*)&sZX[r*DPROJ + gbase + n0] =
            make_float4(acc[i][0],acc[i][1],acc[i][2],acc[i][3]);
      }
    }
    __syncthreads();
  }

  float creg[24];
  #pragma unroll
  for (int j = 0; j < 24; j++) {
    int i = j*256 + tid;
    int l = i / CONVCH, c = i - l*CONVCH;
    float v = conv_w[c*3+0]*sZX[ l   *DPROJ + 64 + c]
            + conv_w[c*3+1]*sZX[(l+1)*DPROJ + 64 + c]
            + conv_w[c*3+2]*sZX[(l+2)*DPROJ + 64 + c]
            + conv_b[c];
    v = siluf(v);
    creg[j] = v;
    if (c >= 128)
      g_Cm[((size_t)seq*LSEQ + c0 + l)*DSTATEV + (c-128)] = v;
  }
  for (int i = tid; i < 32*64; i += 256) {
    int l = i >> 6, j = i & 63;
    g_zs[((size_t)seq*LSEQ + c0 + l)*DINV + j] = siluf(sZX[(l+2)*DPROJ + j]);
  }
  {
    int l = tid >> 3, h = tid & 7;
    float raw = sZX[(l+2)*DPROJ + 256 + h] + dt_bias[h];
    sDT[l*8 + h] = (raw > 20.f) ? raw : log1pf(__expf(raw));
  }
  __syncthreads();

  #pragma unroll
  for (int j = 0; j < 24; j++) {
    int i = j*256 + tid;
    int l = i / CONVCH, c = i - l*CONVCH;
    if (c < 64)       sXH[l*64 + c] = creg[j];
    else if (c < 128) sB[l*64 + (c-64)] = creg[j];
    else              sC[l*68 + (c-128)] = creg[j];
  }
  {
    int w = tid >> 5, lane = tid & 31;
    float Ah = -__expf(A_log[w]);
    float dt = sDT[lane*8 + w];
    float a  = dt * Ah;
    float e1 = __expf(a);
    #pragma unroll
    for (int o = 1; o < 32; o <<= 1) {
      float v = __shfl_up_sync(0xffffffffu, a, o);
      if (lane >= o) a += v;
    }
    sAC[w*33 + lane] = a;
    float alast = __shfl_sync(0xffffffffu, a, 31);
    sED[w*32 + lane] = __expf(alast - a);
    sE1[w*32 + lane] = e1;
    if (lane == 31) g_cd[((size_t)seq*NCHUNKV + chunk)*NHV + w] = __expf(a);
  }
  __syncthreads();

  // Merged: XDT + CF + g_ea + G
  for (int i = tid; i < 32*64; i += 256) {
    int l = i >> 6, d = i & 63;
    float v = sXH[l*64+d]*sDT[l*8 + (d>>3)];
    sXDT[l*64+d] = v;
    sCF[l*68+d]  = v * sED[(d>>3)*32 + l];
  }
  {
    int l = tid >> 3, h = tid & 7;
    g_ea[((size_t)seq*LSEQ + c0 + l)*NHV + h] = __expf(sAC[h*33+l]);
  }
  {
    int w = tid >> 5, l = tid & 31;
    float a0=0.f,a1=0.f,a2=0.f,a3=0.f;
    int s0=w, s1=w+8, s2=w+16, s3=w+24;
    #pragma unroll 4
    for (int n4 = 0; n4 < 64; n4 += 4) {
      float4 cv = *(const float4*)&sC[l*68+n4];
      float4 b0 = *(const float4*)&sB[s0*64+n4];
      float4 b1 = *(const float4*)&sB[s1*64+n4];
      float4 b2 = *(const float4*)&sB[s2*64+n4];
      float4 b3 = *(const float4*)&sB[s3*64+n4];
      a0 += cv.x*b0.x + cv.y*b0.y + cv.z*b0.z + cv.w*b0.w;
      a1 += cv.x*b1.x + cv.y*b1.y + cv.z*b1.z + cv.w*b1.w;
      a2 += cv.x*b2.x + cv.y*b2.y + cv.z*b2.z + cv.w*b2.w;
      a3 += cv.x*b3.x + cv.y*b3.y + cv.z*b3.z + cv.w*b3.w;
    }
    sG[l*33+s0]=a0; sG[l*33+s1]=a1; sG[l*33+s2]=a2; sG[l*33+s3]=a3;
  }
  __syncthreads();

  {
    int nt = tid & 15, ht = tid >> 4;
    int n0 = nt*4, hp0 = ht*4;
    float acc[4][4];
    #pragma unroll
    for (int i = 0; i < 4; i++)
      #pragma unroll
      for (int j = 0; j < 4; j++) acc[i][j] = 0.f;
    #pragma unroll 4
    for (int l = 0; l < 32; l++) {
      float4 cf = *(const float4*)&sCF[l*68 + hp0];
      float4 bv = *(const float4*)&sB[l*64 + n0];
      float cr[4] = {cf.x, cf.y, cf.z, cf.w};
      float br[4] = {bv.x, bv.y, bv.z, bv.w};
      #pragma unroll
      for (int i = 0; i < 4; i++)
        #pragma unroll
        for (int j = 0; j < 4; j++) acc[i][j] += cr[i]*br[j];
    }
    size_t sbase = (((size_t)seq*NCHUNKV + chunk)*NHV)*(HDV*DSTATEV);
    #pragma unroll
    for (int i = 0; i < 4; i++)
      *(float4*)&g_st[sbase + (size_t)(hp0+i)*64 + n0] =
        make_float4(acc[i][0],acc[i][1],acc[i][2],acc[i][3]);
  }

  {
    int l = tid >> 3, h = tid & 7;
    float acc[8];
    #pragma unroll
    for (int p = 0; p < 8; p++) acc[p] = Dp[h]*sXH[l*64 + h*8 + p];
    const float* e1 = sE1 + h*32;
    float w = 1.f;
    for (int s = l; s >= 0; s--) {
      float wgt = sG[l*33+s] * w;
      float4 xa = *(const float4*)&sXDT[s*64 + h*8];
      float4 xb = *(const float4*)&sXDT[s*64 + h*8 + 4];
      acc[0]+=wgt*xa.x; acc[1]+=wgt*xa.y; acc[2]+=wgt*xa.z; acc[3]+=wgt*xa.w;
      acc[4]+=wgt*xb.x; acc[5]+=wgt*xb.y; acc[6]+=wgt*xb.z; acc[7]+=wgt*xb.w;
      w *= e1[s];
    }
    size_t ob = ((size_t)seq*LSEQ + c0 + l)*DINV + h*8;
    *(float4*)&g_y0[ob]   = make_float4(acc[0],acc[1],acc[2],acc[3]);
    *(float4*)&g_y0[ob+4] = make_float4(acc[4],acc[5],acc[6],acc[7]);
  }
}

// ============ k3: inter-chunk scan (states -> prev, in place) ============
__global__ __launch_bounds__(128) void k3_scan() {
  int bid = blockIdx.x;
  int seq = bid >> 3, h = bid & 7;
  int e = threadIdx.x * 4;
  size_t base = (((size_t)seq*NCHUNKV)*NHV + h)*(HDV*DSTATEV) + e;
  size_t cdb  = (size_t)seq*NCHUNKV*NHV + h;
  const size_t CS = (size_t)NHV*HDV*DSTATEV;
  float4 carry = make_float4(0.f,0.f,0.f,0.f);
  for (int c = 0; c < NCHUNKV; c += 4) {
    float4 s0 = *(float4*)&g_st[base];
    float4 s1 = *(float4*)&g_st[base + CS];
    float4 s2 = *(float4*)&g_st[base + 2*CS];
    float4 s3 = *(float4*)&g_st[base + 3*CS];
    float d0 = g_cd[cdb], d1 = g_cd[cdb+8], d2 = g_cd[cdb+16], d3 = g_cd[cdb+24];
    *(float4*)&g_st[base] = carry;
    carry.x = carry.x*d0 + s0.x; carry.y = carry.y*d0 + s0.y;
    carry.z = carry.z*d0 + s0.z; carry.w = carry.w*d0 + s0.w;
    *(float4*)&g_st[base + CS] = carry;
    carry.x = carry.x*d1 + s1.x; carry.y = carry.y*d1 + s1.y;
    carry.z = carry.z*d1 + s1.z; carry.w = carry.w*d1 + s1.w;
    *(float4*)&g_st[base + 2*CS] = carry;
    carry.x = carry.x*d2 + s2.x; carry.y = carry.y*d2 + s2.y;
    carry.z = carry.z*d2 + s2.z; carry.w = carry.w*d2 + s2.w;
    *(float4*)&g_st[base + 3*CS] = carry;
    carry.x = carry.x*d3 + s3.x; carry.y = carry.y*d3 + s3.y;
    carry.z = carry.z*d3 + s3.z; carry.w = carry.w*d3 + s3.w;
    base += 4*CS; cdb += 32;
  }
}

// ============ k4: two chunks/block, batched epilogue loads ============
#define SM4_FLOATS 12992
#define SM4_BYTES (SM4_FLOATS * 4)
__global__ __launch_bounds__(256, 4) void k4_tail(
    const float* __restrict__ rms_w, const float* __restrict__ W_out,
    const float* __restrict__ skip_scale) {
  extern __shared__ float s4[];
  float* sPrev = s4;            // ch*4352 + n*68 + hp
  float* sC    = s4 + 8704;     // l*66 + n
  float* sY    = s4;            // l*68 + hp   (phase 2)
  float* sWo   = s4 + 8704;     // d*32 + m    (phase 2)
  float* sRS   = s4 + 12928;    // [64]
  int cp = blockIdx.x, seq = blockIdx.y;
  int c0 = cp * 64;
  int tid = threadIdx.x;
  float skip = skip_scale[0];

  {
    size_t stb = (((size_t)seq*NCHUNKV + cp*2)*NHV)*(HDV*DSTATEV);
    for (int i = tid; i < 8192; i += 256) {
      int ch = i >> 12, r = i & 4095;
      int hp = r >> 6, n = r & 63;
      sPrev[ch*4352 + n*68 + hp] = g_st[stb + (size_t)ch*4096 + (size_t)hp*64 + n];
    }
  }
  for (int i = tid; i < 4096; i += 256) {
    int l = i >> 6, n = i & 63;
    sC[l*66+n] = g_Cm[((size_t)seq*LSEQ + c0 + l)*DSTATEV + n];
  }
  __syncthreads();

  float yv[4][4];
  int ht = tid & 15, lt = tid >> 4;
  int l0g = lt*4, hp0 = ht*4;
  {
    int ch = lt >> 3;
    const float* Cb = sC + l0g*66;
    const float* Pb = sPrev + ch*4352 + hp0;
    float acc[4][4];
    #pragma unroll
    for (int i = 0; i < 4; i++)
      #pragma unroll
      for (int j = 0; j < 4; j++) acc[i][j] = 0.f;
    #pragma unroll 4
    for (int n = 0; n < 64; n++) {
      float4 pv = *(const float4*)&Pb[n*68];
      float c0v = Cb[n], c1v = Cb[66+n], c2v = Cb[132+n], c3v = Cb[198+n];
      acc[0][0]+=c0v*pv.x; acc[0][1]+=c0v*pv.y; acc[0][2]+=c0v*pv.z; acc[0][3]+=c0v*pv.w;
      acc[1][0]+=c1v*pv.x; acc[1][1]+=c1v*pv.y; acc[1][2]+=c1v*pv.z; acc[1][3]+=c1v*pv.w;
      acc[2][0]+=c2v*pv.x; acc[2][1]+=c2v*pv.y; acc[2][2]+=c2v*pv.z; acc[2][3]+=c2v*pv.w;
      acc[3][0]+=c3v*pv.x; acc[3][1]+=c3v*pv.y; acc[3][2]+=c3v*pv.z; acc[3][3]+=c3v*pv.w;
    }
    // batched epilogue loads: all 12 gmem loads in flight before any use
    int h = hp0 >> 3;
    float ea_r[4]; float4 y0_r[4], zz_r[4];
    #pragma unroll
    for (int i = 0; i < 4; i++) {
      size_t row = (size_t)seq*LSEQ + c0 + l0g + i;
      ea_r[i] = g_ea[row*NHV + h];
      y0_r[i] = *(const float4*)&g_y0[row*DINV + hp0];
      zz_r[i] = *(const float4*)&g_zs[row*DINV + hp0];
    }
    #pragma unroll
    for (int i = 0; i < 4; i++) {
      yv[i][0] = (y0_r[i].x + ea_r[i]*acc[i][0])*zz_r[i].x;
      yv[i][1] = (y0_r[i].y + ea_r[i]*acc[i][1])*zz_r[i].y;
      yv[i][2] = (y0_r[i].z + ea_r[i]*acc[i][2])*zz_r[i].z;
      yv[i][3] = (y0_r[i].w + ea_r[i]*acc[i][3])*zz_r[i].w;
    }
  }
  __syncthreads();
  #pragma unroll
  for (int i = 0; i < 4; i++)
    *(float4*)&sY[(l0g+i)*68 + hp0] = make_float4(yv[i][0],yv[i][1],yv[i][2],yv[i][3]);
  for (int i = tid; i < 2048; i += 256) sWo[i] = W_out[i];
  __syncthreads();

  {
    int w = tid >> 5, lane = tid & 31;
    for (int q = 0; q < 8; q++) {
      int l = w*8 + q;
      float v1 = sY[l*68 + lane], v2 = sY[l*68 + lane + 32];
      float ss = v1*v1 + v2*v2;
      #pragma unroll
      for (int o = 16; o > 0; o >>= 1) ss += __shfl_xor_sync(0xffffffffu, ss, o);
      if (lane == 0) sRS[l] = rsqrtf(ss*(1.f/64.f) + 1e-5f);
    }
  }
  __syncthreads();
  for (int i = tid; i < 4096; i += 256) {
    int l = i >> 6, d = i & 63;
    sY[l*68+d] *= sRS[l]*rms_w[d];
  }
  __syncthreads();
  {
    int mt = tid & 15, lt2 = tid >> 4;
    int l0 = lt2*4, m0 = mt*2;
    // prefetch skip inputs before the d-loop (latency hidden by GEMM2)
    float2 xk_r[4];
    #pragma unroll
    for (int i = 0; i < 4; i++)
      xk_r[i] = *(const float2*)&g_xs[((size_t)seq*LSEQ + c0 + l0 + i)*DMV + m0];
    float acc[4][2];
    #pragma unroll
    for (int i = 0; i < 4; i++) { acc[i][0] = 0.f; acc[i][1] = 0.f; }
    const float* Yb = sY + l0*68;
    #pragma unroll 4
    for (int d = 0; d < 64; d++) {
      float2 wv = *(const float2*)&sWo[d*32 + m0];
      float y0v = Yb[d], y1v = Yb[68+d], y2v = Yb[136+d], y3v = Yb[204+d];
      acc[0][0]+=y0v*wv.x; acc[0][1]+=y0v*wv.y;
      acc[1][0]+=y1v*wv.x; acc[1][1]+=y1v*wv.y;
      acc[2][0]+=y2v*wv.x; acc[2][1]+=y2v*wv.y;
      acc[3][0]+=y3v*wv.x; acc[3][1]+=y3v*wv.y;
    }
    int split = seq >> 3, b = seq & 7;
    #pragma unroll
    for (int i = 0; i < 4; i++) {
      int l = l0 + i;
      float2 ov;
      ov.x = acc[i][0] + skip*xk_r[i].x;
      ov.y = acc[i][1] + skip*xk_r[i].y;
      *(float2*)&g_ym[((size_t)b*LSEQ + c0 + l)*CINV + split*32 + m0] = ov;
    }
  }
}

// ============ k5: LN + 256x256 projection, float4-k x-loads ============
#define SM5_FLOATS 26880
#define SM5_BYTES (SM5_FLOATS * 4)
__global__ __launch_bounds__(256, 2) void k5_out(
    const float* __restrict__ lw, const float* __restrict__ lb,
    const float* __restrict__ proj_w, const float* __restrict__ proj_b,
    float* __restrict__ out) {
  extern __shared__ float sm[];
  float* sX = sm;           // [64][260]
  float* sW = sm + 16640;   // [32][320] swizzled: addr = k*320 + (o>>4)*20 + (o&15)
  int b = blockIdx.y;
  int l0 = blockIdx.x * 64;
  int tid = threadIdx.x;

  float wbuf[32];
  #pragma unroll
  for (int j = 0; j < 32; j++) {
    int i = tid + j*256;
    int k = i >> 8, o = i & 255;
    wbuf[j] = proj_w[(size_t)k*DOUTV + o];
  }

  for (int i = tid; i < 64*256; i += 256) {
    int l = i >> 8, c = i & 255;
    sX[l*260 + c] = g_ym[((size_t)b*LSEQ + l0 + l)*CINV + c];
  }
  __syncthreads();
  {
    int w = tid >> 5, lane = tid & 31;
    for (int q = 0; q < 8; q++) {
      int l = w*8 + q;
      float s = 0.f, ss = 0.f;
      #pragma unroll
      for (int j = 0; j < 8; j++) {
        float v = sX[l*260 + lane + 32*j];
        s += v; ss += v*v;
      }
      #pragma unroll
      for (int o = 16; o > 0; o >>= 1) {
        s  += __shfl_xor_sync(0xffffffffu, s,  o);
        ss += __shfl_xor_sync(0xffffffffu, ss, o);
      }
      float mu = s * (1.f/256.f);
      float rs = rsqrtf(ss*(1.f/256.f) - mu*mu + 1e-5f);
      #pragma unroll
      for (int j = 0; j < 8; j++) {
        int c = lane + 32*j;
        sX[l*260 + c] = (sX[l*260 + c] - mu)*rs*lw[c] + lb[c];
      }
    }
  }
  __syncthreads();

  int ot = tid & 15, lt = tid >> 4;
  float acc[4][16];
  #pragma unroll
  for (int i = 0; i < 4; i++)
    #pragma unroll
    for (int j = 0; j < 16; j++) acc[i][j] = 0.f;

  for (int s = 0; s < 8; s++) {
    #pragma unroll
    for (int j = 0; j < 32; j++) {
      int i = tid + j*256;
      int k = i >> 8, o = i & 255;
      sW[k*320 + (o>>4)*20 + (o&15)] = wbuf[j];
    }
    __syncthreads();
    if (s < 7) {
      #pragma unroll
      for (int j = 0; j < 32; j++) {
        int i = tid + j*256;
        int k = i >> 8, o = i & 255;
        wbuf[j] = proj_w[(size_t)((s+1)*32 + k)*DOUTV + o];
      }
    }
    const float* xb = sX + lt*4*260 + s*32;
    for (int k0 = 0; k0 < 32; k0 += 4) {
      float xq[4][4];
      #pragma unroll
      for (int i = 0; i < 4; i++)
        *(float4*)&xq[i][0] = *(const float4*)&xb[i*260 + k0];
      #pragma unroll
      for (int kk = 0; kk < 4; kk++) {
        const float* wrow = sW + (k0+kk)*320 + ot*20;
        float4 w0 = *(const float4*)&wrow[0];
        float4 w1 = *(const float4*)&wrow[4];
        float4 w2 = *(const float4*)&wrow[8];
        float4 w3 = *(const float4*)&wrow[12];
        float wr[16] = {w0.x,w0.y,w0.z,w0.w, w1.x,w1.y,w1.z,w1.w,
                        w2.x,w2.y,w2.z,w2.w, w3.x,w3.y,w3.z,w3.w};
        #pragma unroll
        for (int i = 0; i < 4; i++)
          #pragma unroll
          for (int j = 0; j < 16; j++) acc[i][j] += xq[i][kk]*wr[j];
      }
    }
    __syncthreads();
  }

  #pragma unroll
  for (int j = 0; j < 16; j++) {
    int O = ot*16 + j;
    float bb = proj_b[O];
    float4 ov = make_float4(acc[0][j]+bb, acc[1][j]+bb, acc[2][j]+bb, acc[3][j]+bb);
    *(float4*)&out[((size_t)(b*DOUTV + O))*LSEQ + l0 + lt*4] = ov;
  }
}

extern "C" void kernel_launch(void* const* d_in, const int* in_sizes, int n_in,
                              void* d_out, int out_size) {
  const float* x        = (const float*)d_in[0];
  const float* ln_w     = (const float*)d_in[1];
  const float* ln_b     = (const float*)d_in[2];
  const float* skip_s   = (const float*)d_in[3];
  const float* proj_w   = (const float*)d_in[4];
  const float* proj_b   = (const float*)d_in[5];
  const float* W_in     = (const float*)d_in[6];
  const float* conv_w   = (const float*)d_in[7];
  const float* conv_b   = (const float*)d_in[8];
  const float* dt_bias  = (const float*)d_in[9];
  const float* A_log    = (const float*)d_in[10];
  const float* Dp       = (const float*)d_in[11];
  const float* rms_w    = (const float*)d_in[12];
  const float* W_out    = (const float*)d_in[13];
  float* out = (float*)d_out;

  cudaFuncSetAttribute(k2_chunk, cudaFuncAttributeMaxDynamicSharedMemorySize, SM2_BYTES);
  cudaFuncSetAttribute(k4_tail,  cudaFuncAttributeMaxDynamicSharedMemorySize, SM4_BYTES);
  cudaFuncSetAttribute(k5_out,   cudaFuncAttributeMaxDynamicSharedMemorySize, SM5_BYTES);

  k1_ln_split<<<dim3(288, 8), 256>>>(x, ln_w, ln_b);
  k2_chunk<<<dim3(NCHUNKV, NSEQV), 256, SM2_BYTES>>>(W_in, conv_w, conv_b, dt_bias, A_log, Dp);
  k3_scan<<<512, 128>>>();
  k4_tail<<<dim3(144, NSEQV), 256, SM4_BYTES>>>(rms_w, W_out, skip_s);
  k5_out<<<dim3(144, 8), 256, SM5_BYTES>>>(ln_w, ln_b, proj_w, proj_b, out);
}